// round 5
// baseline (speedup 1.0000x reference)
#include <cuda_runtime.h>
#include <math.h>
#include <stdint.h>

#define VOCAB 50000
#define EMB   300
#define SEQ   80
#define HID   128
#define BATCH 4096

typedef unsigned long long ull;

// Scratch: projected embedding table P = emb @ Wxh (25.6 MB, L2-resident at use)
__device__ float g_P[VOCAB * HID];

// ---- packed f32x2 helpers ----
__device__ __forceinline__ ull fma2(ull a, ull b, ull c) {
    ull d; asm("fma.rn.f32x2 %0, %1, %2, %3;" : "=l"(d) : "l"(a), "l"(b), "l"(c)); return d;
}
__device__ __forceinline__ ull add2(ull a, ull b) {
    ull d; asm("add.rn.f32x2 %0, %1, %2;" : "=l"(d) : "l"(a), "l"(b)); return d;
}
__device__ __forceinline__ ull pk(float lo, float hi) {
    ull d; asm("mov.b64 %0, {%1, %2};" : "=l"(d) : "f"(lo), "f"(hi)); return d;
}
__device__ __forceinline__ float2 upk(ull v) {
    float2 r; asm("mov.b64 {%0, %1}, %2;" : "=f"(r.x), "=f"(r.y) : "l"(v)); return r;
}
// clamp-free tanh: saturates correctly via exp overflow/underflow
__device__ __forceinline__ float ftanh(float x) {
    float e = __expf(2.f * x);
    return 1.f - __fdividef(2.f, e + 1.f);
}

// ---------------------------------------------------------------------------
// Kernel A: P[v][j] = sum_e emb[v][e] * Wxh[e][j]
// 128x128 tile, TK=12 (300 = 25*12), double-buffered smem (24 KB total)
// -> 2 blocks/SM (4 warps/SMSP). 8x8 per-thread scalar-FFMA tile.
// ---------------------------------------------------------------------------
#define PTK 12

__global__ __launch_bounds__(256, 2) void proj_kernel(const float* __restrict__ emb,
                                                      const float* __restrict__ Wxh) {
    __shared__ float As[2][PTK][128];   // [buf][k][row]
    __shared__ float Bs[2][PTK][128];   // [buf][k][col]

    const int tid = threadIdx.x;
    const int v0  = blockIdx.x * 128;
    const int tr  = tid >> 4;   // rows tr*8..+7
    const int tc  = tid & 15;   // cols tc*8..+7

    float acc[8][8];
#pragma unroll
    for (int i = 0; i < 8; i++)
#pragma unroll
        for (int j = 0; j < 8; j++) acc[i][j] = 0.f;

    const bool isA = (tid < 128);
    int av = v0 + tid; if (av > VOCAB - 1) av = VOCAB - 1;   // clamped junk row, discarded
    const int t2   = tid - 128;
    const int brow = t2 >> 5;          // 0..3
    const int bcol = (t2 & 31) * 4;

    float4 pf[3];
#pragma unroll
    for (int q = 0; q < 3; q++) {
        if (isA) pf[q] = *(const float4*)&emb[(long)av * EMB + q * 4];
        else     pf[q] = *(const float4*)&Wxh[(q * 4 + brow) * HID + bcol];
    }

    for (int it = 0; it < 25; it++) {
        const int pb = it & 1;
        if (isA) {
#pragma unroll
            for (int q = 0; q < 3; q++) {
                As[pb][q * 4 + 0][tid] = pf[q].x;
                As[pb][q * 4 + 1][tid] = pf[q].y;
                As[pb][q * 4 + 2][tid] = pf[q].z;
                As[pb][q * 4 + 3][tid] = pf[q].w;
            }
        } else {
#pragma unroll
            for (int q = 0; q < 3; q++)
                *(float4*)&Bs[pb][q * 4 + brow][bcol] = pf[q];
        }
        __syncthreads();

        if (it + 1 < 25) {
            const int e0 = (it + 1) * PTK;
#pragma unroll
            for (int q = 0; q < 3; q++) {
                if (isA) pf[q] = *(const float4*)&emb[(long)av * EMB + e0 + q * 4];
                else     pf[q] = *(const float4*)&Wxh[(e0 + q * 4 + brow) * HID + bcol];
            }
        }

#pragma unroll
        for (int k = 0; k < PTK; k++) {
            float a[8], b[8];
            *(float4*)&a[0] = *(const float4*)&As[pb][k][tr * 8];
            *(float4*)&a[4] = *(const float4*)&As[pb][k][tr * 8 + 4];
            *(float4*)&b[0] = *(const float4*)&Bs[pb][k][tc * 8];
            *(float4*)&b[4] = *(const float4*)&Bs[pb][k][tc * 8 + 4];
#pragma unroll
            for (int i = 0; i < 8; i++)
#pragma unroll
                for (int j = 0; j < 8; j++) acc[i][j] += a[i] * b[j];
        }
        __syncthreads();
    }

#pragma unroll
    for (int i = 0; i < 8; i++) {
        const int v = v0 + tr * 8 + i;
        if (v < VOCAB) {
            *(float4*)&g_P[(long)v * HID + tc * 8]     = *(float4*)&acc[i][0];
            *(float4*)&g_P[(long)v * HID + tc * 8 + 4] = *(float4*)&acc[i][4];
        }
    }
}

// ---------------------------------------------------------------------------
// Kernel B: recurrence. grid=128, 256 threads (8 warps = 4 rowgroups x
// 2 colgroups -> 2 warps per SMSP). Block = 32 batch rows.
// Warp = 8 rows x 64 cols; thread = 8 rows x 2 cols (j0 = cg*64 + 2*lane).
// h buffer: [k][row] 16 KB, double-buffered, 16B units XOR-swizzled by
// ((j>>1)&7) -> conflict-free stores, broadcast reads.
// Per thread/k: 2 LDS.128 (h row-pairs, feed fma2 directly) + 1 LDS.64 (w)
// + 2 dup movs + 8 fma2  =>  crossbar 32 wf/k/SM == fma2 pipe 32 cyc/k.
// One __syncthreads per timestep.
// ---------------------------------------------------------------------------
__global__ __launch_bounds__(256, 1) void rnn_kernel(const int* __restrict__ x,
                                                     const float* __restrict__ Whh,
                                                     const float* __restrict__ bh,
                                                     const float* __restrict__ Wd,
                                                     const float* __restrict__ bd,
                                                     float* __restrict__ out) {
    extern __shared__ char smc[];
    float* Whh_sh = (float*)smc;                       // 65536 B
    char*  hbuf   = smc + 65536;                       // 2 x 16384 B
    int*   tok_sh = (int*)(smc + 65536 + 32768);       // 10240 B
    float* red    = (float*)(smc + 65536 + 32768 + 10240);  // 64 floats

    const int tid  = threadIdx.x;
    const int lane = tid & 31;
    const int wid  = tid >> 5;
    const int rg   = wid & 3;          // rowgroup 0..3 (SMSP id)
    const int cg   = wid >> 2;         // colgroup 0..1
    const int j0   = cg * 64 + 2 * lane;
    const int b0   = blockIdx.x * 32;

    // ---- init: Whh + tokens ----
    {
        const float4* s = (const float4*)Whh;
        float4* d = (float4*)Whh_sh;
        for (int i = tid; i < HID * HID / 4; i += 256) d[i] = s[i];
        const int4* xs = (const int4*)(x + b0 * SEQ);
        int4* td = (int4*)tok_sh;
        for (int i = tid; i < 32 * SEQ / 4; i += 256) td[i] = xs[i];
    }
    __syncthreads();

    const int* myTok = tok_sh + (rg * 8) * SEQ;
    const int  sw    = lane & 7;           // == ((j0>>1)&7) == ((j0+1)>>1)&7
    const int  ub    = rg * 2;             // base unit-in-group for this rowgroup

    const ull bh2[2] = { pk(bh[j0], bh[j0]), pk(bh[j0 + 1], bh[j0 + 1]) };

    // prefetch t=0 inputs: P[tok][j0..j0+1] for 8 rows
    float2 xv[8];
#pragma unroll
    for (int r = 0; r < 8; r++) {
        const int tk = myTok[r * SEQ + 0];
        xv[r] = *(const float2*)(g_P + tk * HID + j0);
    }

    float2 tv[4][2];   // last tanh values: [row-pair][col]

    for (int t = 0; t < SEQ; t++) {
        ull acc[4][2];
#pragma unroll
        for (int p = 0; p < 4; p++) {
            acc[p][0] = add2(pk(xv[2 * p].x, xv[2 * p + 1].x), bh2[0]);
            acc[p][1] = add2(pk(xv[2 * p].y, xv[2 * p + 1].y), bh2[1]);
        }

        // prefetch next timestep's P rows
        if (t + 1 < SEQ) {
#pragma unroll
            for (int r = 0; r < 8; r++) {
                const int tk = myTok[r * SEQ + t + 1];
                xv[r] = *(const float2*)(g_P + tk * HID + j0);
            }
        }

        if (t > 0) {
            const char* hb = hbuf + ((t & 1) ^ 1) * 16384;   // h(t-1)
            const float* wp = Whh_sh + j0;
#pragma unroll 1
            for (int ko = 0; ko < 8; ko++) {
#pragma unroll
                for (int ki = 0; ki < 16; ki++) {
                    const int kp = ko * 16 + ki;
                    const int xk = (kp >> 1) & 7;
                    const char* hk = hb + kp * 128;
                    ulonglong2 hA = *(const ulonglong2*)(hk + ((ub)     ^ xk) * 16);
                    ulonglong2 hB = *(const ulonglong2*)(hk + ((ub + 1) ^ xk) * 16);
                    float2 w = *(const float2*)(wp + kp * HID);
                    ull w0 = pk(w.x, w.x), w1 = pk(w.y, w.y);
                    acc[0][0] = fma2(hA.x, w0, acc[0][0]);
                    acc[0][1] = fma2(hA.x, w1, acc[0][1]);
                    acc[1][0] = fma2(hA.y, w0, acc[1][0]);
                    acc[1][1] = fma2(hA.y, w1, acc[1][1]);
                    acc[2][0] = fma2(hB.x, w0, acc[2][0]);
                    acc[2][1] = fma2(hB.x, w1, acc[2][1]);
                    acc[3][0] = fma2(hB.y, w0, acc[3][0]);
                    acc[3][1] = fma2(hB.y, w1, acc[3][1]);
                }
            }
        }

        // tanh
#pragma unroll
        for (int p = 0; p < 4; p++) {
#pragma unroll
            for (int c = 0; c < 2; c++) {
                float2 a = upk(acc[p][c]);
                tv[p][c].x = ftanh(a.x);
                tv[p][c].y = ftanh(a.y);
            }
        }
        // store h(t) to buf t&1: for each of 2 cols, 2 units of 4 rows
        {
            char* hn = hbuf + (t & 1) * 16384;
#pragma unroll
            for (int c = 0; c < 2; c++) {
                const int j = j0 + c;
                char* hj = hn + j * 128;
#pragma unroll
                for (int u = 0; u < 2; u++) {
                    float4 v;
                    v.x = tv[2 * u][c].x;     v.y = tv[2 * u][c].y;
                    v.z = tv[2 * u + 1][c].x; v.w = tv[2 * u + 1][c].y;
                    *(float4*)(hj + ((ub + u) ^ sw) * 16) = v;
                }
            }
        }
        __syncthreads();
    }

    // ---- Dense(1) + sigmoid from register-resident final h ----
    const float wd0 = Wd[j0], wd1 = Wd[j0 + 1];
    float part[8];
#pragma unroll
    for (int p = 0; p < 4; p++) {
        part[2 * p]     = tv[p][0].x * wd0 + tv[p][1].x * wd1;
        part[2 * p + 1] = tv[p][0].y * wd0 + tv[p][1].y * wd1;
    }
#pragma unroll
    for (int off = 16; off > 0; off >>= 1)
#pragma unroll
        for (int r = 0; r < 8; r++)
            part[r] += __shfl_xor_sync(0xffffffff, part[r], off);
    if (lane == 0) {
#pragma unroll
        for (int r = 0; r < 8; r++)
            red[(rg * 8 + r) * 2 + cg] = part[r];
    }
    __syncthreads();
    if (tid < 32) {
        const float s = red[tid * 2] + red[tid * 2 + 1] + bd[0];
        out[b0 + tid] = __fdividef(1.f, 1.f + __expf(-s));
    }
}

// ---------------------------------------------------------------------------
extern "C" void kernel_launch(void* const* d_in, const int* in_sizes, int n_in,
                              void* d_out, int out_size) {
    const int*   x   = (const int*)d_in[0];
    const float* emb = (const float*)d_in[1];
    const float* Wxh = (const float*)d_in[2];
    const float* Whh = (const float*)d_in[3];
    const float* bh  = (const float*)d_in[4];
    const float* Wd  = (const float*)d_in[5];
    const float* bd  = (const float*)d_in[6];
    float* out = (float*)d_out;

    proj_kernel<<<(VOCAB + 127) / 128, 256>>>(emb, Wxh);

    const int smem = 65536 + 32768 + 10240 + 64 * 4;   // 108800 B
    cudaFuncSetAttribute(rnn_kernel, cudaFuncAttributeMaxDynamicSharedMemorySize, smem);
    rnn_kernel<<<BATCH / 32, 256, smem>>>(x, Whh, bh, Wd, bd, out);
}

// round 7
// speedup vs baseline: 1.0026x; 1.0026x over previous
#include <cuda_runtime.h>
#include <math.h>
#include <stdint.h>

#define VOCAB 50000
#define EMB   300
#define SEQ   80
#define HID   128
#define BATCH 4096

typedef unsigned long long ull;

// Scratch: projected embedding table P = emb @ Wxh (25.6 MB, L2-resident at use)
__device__ float g_P[VOCAB * HID];

// ---- packed f32x2 helpers ----
__device__ __forceinline__ ull fma2(ull a, ull b, ull c) {
    ull d; asm("fma.rn.f32x2 %0, %1, %2, %3;" : "=l"(d) : "l"(a), "l"(b), "l"(c)); return d;
}
__device__ __forceinline__ ull add2(ull a, ull b) {
    ull d; asm("add.rn.f32x2 %0, %1, %2;" : "=l"(d) : "l"(a), "l"(b)); return d;
}
__device__ __forceinline__ ull pk(float lo, float hi) {
    ull d; asm("mov.b64 %0, {%1, %2};" : "=l"(d) : "f"(lo), "f"(hi)); return d;
}
__device__ __forceinline__ float2 upk(ull v) {
    float2 r; asm("mov.b64 {%0, %1}, %2;" : "=f"(r.x), "=f"(r.y) : "l"(v)); return r;
}
__device__ __forceinline__ ull shfl64(ull v, int src) {
    uint32_t lo = (uint32_t)v, hi = (uint32_t)(v >> 32);
    lo = __shfl_sync(0xffffffffu, lo, src);
    hi = __shfl_sync(0xffffffffu, hi, src);
    return ((ull)hi << 32) | (ull)lo;
}
// clamp-free tanh (saturates via exp overflow/underflow); matches winner's
__device__ __forceinline__ float ftanh(float x) {
    float e = __expf(2.f * x);
    return 1.f - __fdividef(2.f, e + 1.f);
}

// ---------------------------------------------------------------------------
// Kernel A: P[v][j] = sum_e emb[v][e] * Wxh[e][j]
// (exact 372.8-winner version: PTK=20, double-buffered, 1 sync/iter)
// ---------------------------------------------------------------------------
#define PTK 20

__global__ __launch_bounds__(256) void proj_kernel(const float* __restrict__ emb,
                                                   const float* __restrict__ Wxh) {
    __shared__ float As[2][PTK][128];   // [buf][k][row]
    __shared__ float Bs[2][PTK][128];   // [buf][k][col]

    const int tid = threadIdx.x;
    const int v0  = blockIdx.x * 128;
    const int tr  = tid >> 4;   // rows tr*8..+7
    const int tc  = tid & 15;   // cols tc*8..+7

    float acc[8][8];
#pragma unroll
    for (int i = 0; i < 8; i++)
#pragma unroll
        for (int j = 0; j < 8; j++) acc[i][j] = 0.f;

    const bool isA = (tid < 128);
    int av = v0 + tid; if (av > VOCAB - 1) av = VOCAB - 1;   // clamped junk row, discarded
    const int t2   = tid - 128;
    const int brow = t2 >> 5;        // 0..3
    const int bcol = (t2 & 31) * 4;

    float4 pf[5];
#pragma unroll
    for (int q = 0; q < 5; q++) {
        if (isA) pf[q] = *(const float4*)&emb[(long)av * EMB + 0 + q * 4];
        else     pf[q] = *(const float4*)&Wxh[(0 + q * 4 + brow) * HID + bcol];
    }

    for (int it = 0; it < 15; it++) {
        const int pb = it & 1;
        if (isA) {
#pragma unroll
            for (int q = 0; q < 5; q++) {
                As[pb][q * 4 + 0][tid] = pf[q].x;
                As[pb][q * 4 + 1][tid] = pf[q].y;
                As[pb][q * 4 + 2][tid] = pf[q].z;
                As[pb][q * 4 + 3][tid] = pf[q].w;
            }
        } else {
#pragma unroll
            for (int q = 0; q < 5; q++)
                *(float4*)&Bs[pb][q * 4 + brow][bcol] = pf[q];
        }
        __syncthreads();

        if (it + 1 < 15) {
            const int e0 = (it + 1) * PTK;
#pragma unroll
            for (int q = 0; q < 5; q++) {
                if (isA) pf[q] = *(const float4*)&emb[(long)av * EMB + e0 + q * 4];
                else     pf[q] = *(const float4*)&Wxh[(e0 + q * 4 + brow) * HID + bcol];
            }
        }

#pragma unroll
        for (int k = 0; k < PTK; k++) {
            float a[8], b[8];
            *(float4*)&a[0] = *(const float4*)&As[pb][k][tr * 8];
            *(float4*)&a[4] = *(const float4*)&As[pb][k][tr * 8 + 4];
            *(float4*)&b[0] = *(const float4*)&Bs[pb][k][tc * 8];
            *(float4*)&b[4] = *(const float4*)&Bs[pb][k][tc * 8 + 4];
#pragma unroll
            for (int i = 0; i < 8; i++)
#pragma unroll
                for (int j = 0; j < 8; j++) acc[i][j] += a[i] * b[j];
        }
        __syncthreads();
    }

#pragma unroll
    for (int i = 0; i < 8; i++) {
        const int v = v0 + tr * 8 + i;
        if (v < VOCAB) {
            *(float4*)&g_P[(long)v * HID + tc * 8]     = *(float4*)&acc[i][0];
            *(float4*)&g_P[(long)v * HID + tc * 8 + 4] = *(float4*)&acc[i][4];
        }
    }
}

// ---------------------------------------------------------------------------
// Kernel B: recurrence with h ENTIRELY IN REGISTERS, distributed via shfl.
// grid=128, 128 threads (4 warps, 1/SMSP). Warp = 8 batch rows x 128 cols;
// lane owns cols j0=4*lane..+3, holding tv[p][c] = pk(h[2p][j0+c], h[2p+1][j0+c]).
// For k-column of h: owner lane = k>>2, register tv[p][k&3] -> shfl64 broadcast.
// Per k: 8 SHFL + 1 LDS.128 (Whh row) + 4 dup movs + 16 fma2.
// NO smem h, NO stores, NO barriers in the timestep loop.
// ---------------------------------------------------------------------------
__global__ __launch_bounds__(128, 1) void rnn_kernel(const int* __restrict__ x,
                                                     const float* __restrict__ Whh,
                                                     const float* __restrict__ bh,
                                                     const float* __restrict__ Wd,
                                                     const float* __restrict__ bd,
                                                     float* __restrict__ out) {
    extern __shared__ char smc[];
    float* Whh_sh = (float*)smc;                 // 65536 B
    int*   tok_sh = (int*)(smc + 65536);         // 10240 B

    const int tid  = threadIdx.x;
    const int lane = tid & 31;
    const int rg   = tid >> 5;
    const int j0   = lane * 4;
    const int b0   = blockIdx.x * 32;

    // ---- init: Whh + tokens into smem ----
    {
        const float4* s = (const float4*)Whh;
        float4* d = (float4*)Whh_sh;
        for (int i = tid; i < HID * HID / 4; i += 128) d[i] = s[i];
        const int4* xs = (const int4*)(x + b0 * SEQ);
        int4* td = (int4*)tok_sh;
        for (int i = tid; i < 32 * SEQ / 4; i += 128) td[i] = xs[i];
    }
    __syncthreads();

    const int* myTok = tok_sh + (rg * 8) * SEQ;

    const float4 bh4 = *(const float4*)(bh + j0);
    ull bhd[4] = {pk(bh4.x, bh4.x), pk(bh4.y, bh4.y), pk(bh4.z, bh4.z), pk(bh4.w, bh4.w)};

    // prefetch t=0 inputs: P[tok][j0..j0+3] for this thread's 8 rows
    float4 xraw[8];
#pragma unroll
    for (int r = 0; r < 8; r++) {
        const int tk = myTok[r * SEQ + 0];
        xraw[r] = *(const float4*)(g_P + tk * HID + j0);
    }

    // h state: tv[p][c] = pk(h[2p][j0+c], h[2p+1][j0+c])
    ull tv[4][4];
#pragma unroll
    for (int p = 0; p < 4; p++)
#pragma unroll
        for (int c = 0; c < 4; c++) tv[p][c] = 0ull;

    const float* wrow = Whh_sh + j0;

    for (int t = 0; t < SEQ; t++) {
        ull acc[4][4];
#pragma unroll
        for (int p = 0; p < 4; p++) {
            const float* lo = (const float*)&xraw[2 * p];
            const float* hi = (const float*)&xraw[2 * p + 1];
#pragma unroll
            for (int c = 0; c < 4; c++)
                acc[p][c] = add2(pk(lo[c], hi[c]), bhd[c]);
        }

        // prefetch next timestep's P rows (consumed next iteration)
        if (t + 1 < SEQ) {
#pragma unroll
            for (int r = 0; r < 8; r++) {
                const int tk = myTok[r * SEQ + t + 1];
                xraw[r] = *(const float4*)(g_P + tk * HID + j0);
            }
        }

        if (t > 0) {
#pragma unroll 1
            for (int k0 = 0; k0 < HID; k0 += 16) {
#pragma unroll
                for (int kk = 0; kk < 16; kk++) {
                    const int k   = k0 + kk;
                    const int src = k >> 2;       // uniform across warp
                    const int c   = kk & 3;       // compile-time (k0 % 4 == 0)
                    // h column k, packed row pairs, from owner lane's registers
                    const ull h01 = shfl64(tv[0][c], src);
                    const ull h23 = shfl64(tv[1][c], src);
                    const ull h45 = shfl64(tv[2][c], src);
                    const ull h67 = shfl64(tv[3][c], src);
                    const float4 w = *(const float4*)(wrow + k * HID);
                    const ull w0 = pk(w.x, w.x), w1 = pk(w.y, w.y);
                    const ull w2 = pk(w.z, w.z), w3 = pk(w.w, w.w);
                    acc[0][0] = fma2(h01, w0, acc[0][0]);
                    acc[0][1] = fma2(h01, w1, acc[0][1]);
                    acc[0][2] = fma2(h01, w2, acc[0][2]);
                    acc[0][3] = fma2(h01, w3, acc[0][3]);
                    acc[1][0] = fma2(h23, w0, acc[1][0]);
                    acc[1][1] = fma2(h23, w1, acc[1][1]);
                    acc[1][2] = fma2(h23, w2, acc[1][2]);
                    acc[1][3] = fma2(h23, w3, acc[1][3]);
                    acc[2][0] = fma2(h45, w0, acc[2][0]);
                    acc[2][1] = fma2(h45, w1, acc[2][1]);
                    acc[2][2] = fma2(h45, w2, acc[2][2]);
                    acc[2][3] = fma2(h45, w3, acc[2][3]);
                    acc[3][0] = fma2(h67, w0, acc[3][0]);
                    acc[3][1] = fma2(h67, w1, acc[3][1]);
                    acc[3][2] = fma2(h67, w2, acc[3][2]);
                    acc[3][3] = fma2(h67, w3, acc[3][3]);
                }
            }
        }

        // tanh -> new tv (registers only; MUFU ILP: exps batched by ptxas)
#pragma unroll
        for (int p = 0; p < 4; p++)
#pragma unroll
            for (int c = 0; c < 4; c++) {
                float2 a = upk(acc[p][c]);
                tv[p][c] = pk(ftanh(a.x), ftanh(a.y));
            }
    }

    // ---- Dense(1) + sigmoid from register-resident final h ----
    const float4 wd4 = *(const float4*)(Wd + j0);
    const float* wdp = (const float*)&wd4;
    const float  bd0 = bd[0];
    float part[8];
#pragma unroll
    for (int r = 0; r < 8; r++) part[r] = 0.f;
#pragma unroll
    for (int p = 0; p < 4; p++)
#pragma unroll
        for (int c = 0; c < 4; c++) {
            float2 v = upk(tv[p][c]);
            part[2 * p]     += v.x * wdp[c];
            part[2 * p + 1] += v.y * wdp[c];
        }
#pragma unroll
    for (int off = 16; off > 0; off >>= 1)
#pragma unroll
        for (int r = 0; r < 8; r++)
            part[r] += __shfl_xor_sync(0xffffffff, part[r], off);
    if (lane == 0) {
#pragma unroll
        for (int r = 0; r < 8; r++)
            out[b0 + rg * 8 + r] = __fdividef(1.f, 1.f + __expf(-(part[r] + bd0)));
    }
}

// ---------------------------------------------------------------------------
extern "C" void kernel_launch(void* const* d_in, const int* in_sizes, int n_in,
                              void* d_out, int out_size) {
    const int*   x   = (const int*)d_in[0];
    const float* emb = (const float*)d_in[1];
    const float* Wxh = (const float*)d_in[2];
    const float* Whh = (const float*)d_in[3];
    const float* bh  = (const float*)d_in[4];
    const float* Wd  = (const float*)d_in[5];
    const float* bd  = (const float*)d_in[6];
    float* out = (float*)d_out;

    proj_kernel<<<(VOCAB + 127) / 128, 256>>>(emb, Wxh);

    const int smem = 65536 + 32 * SEQ * 4;   // 75776 B
    cudaFuncSetAttribute(rnn_kernel, cudaFuncAttributeMaxDynamicSharedMemorySize, smem);
    rnn_kernel<<<BATCH / 32, 128, smem>>>(x, Whh, bh, Wd, bd, out);
}

// round 8
// speedup vs baseline: 1.0291x; 1.0264x over previous
#include <cuda_runtime.h>
#include <math.h>
#include <stdint.h>

#define VOCAB 50000
#define EMB   300
#define SEQ   80
#define HID   128
#define BATCH 4096

typedef unsigned long long ull;

// Scratch: projected embedding table P = emb @ Wxh (25.6 MB, L2-resident at use)
__device__ float g_P[VOCAB * HID];

// ---- packed f32x2 helpers ----
__device__ __forceinline__ ull fma2(ull a, ull b, ull c) {
    ull d; asm("fma.rn.f32x2 %0, %1, %2, %3;" : "=l"(d) : "l"(a), "l"(b), "l"(c)); return d;
}
__device__ __forceinline__ ull add2(ull a, ull b) {
    ull d; asm("add.rn.f32x2 %0, %1, %2;" : "=l"(d) : "l"(a), "l"(b)); return d;
}
__device__ __forceinline__ ull pk(float lo, float hi) {
    ull d; asm("mov.b64 %0, {%1, %2};" : "=l"(d) : "f"(lo), "f"(hi)); return d;
}
__device__ __forceinline__ float2 upk(ull v) {
    float2 r; asm("mov.b64 {%0, %1}, %2;" : "=f"(r.x), "=f"(r.y) : "l"(v)); return r;
}
// clamp-free tanh (saturates via exp overflow/underflow)
__device__ __forceinline__ float ftanh(float x) {
    float e = __expf(2.f * x);
    return 1.f - __fdividef(2.f, e + 1.f);
}

// ---------------------------------------------------------------------------
// Kernel A: P[v][j] = sum_e emb[v][e] * Wxh[e][j]
// (exact 372.8-winner version: PTK=20, double-buffered, 1 sync/iter)
// ---------------------------------------------------------------------------
#define PTK 20

__global__ __launch_bounds__(256) void proj_kernel(const float* __restrict__ emb,
                                                   const float* __restrict__ Wxh) {
    __shared__ float As[2][PTK][128];   // [buf][k][row]
    __shared__ float Bs[2][PTK][128];   // [buf][k][col]

    const int tid = threadIdx.x;
    const int v0  = blockIdx.x * 128;
    const int tr  = tid >> 4;   // rows tr*8..+7
    const int tc  = tid & 15;   // cols tc*8..+7

    float acc[8][8];
#pragma unroll
    for (int i = 0; i < 8; i++)
#pragma unroll
        for (int j = 0; j < 8; j++) acc[i][j] = 0.f;

    const bool isA = (tid < 128);
    int av = v0 + tid; if (av > VOCAB - 1) av = VOCAB - 1;   // clamped junk row, discarded
    const int t2   = tid - 128;
    const int brow = t2 >> 5;        // 0..3
    const int bcol = (t2 & 31) * 4;

    float4 pf[5];
#pragma unroll
    for (int q = 0; q < 5; q++) {
        if (isA) pf[q] = *(const float4*)&emb[(long)av * EMB + 0 + q * 4];
        else     pf[q] = *(const float4*)&Wxh[(0 + q * 4 + brow) * HID + bcol];
    }

    for (int it = 0; it < 15; it++) {
        const int pb = it & 1;
        if (isA) {
#pragma unroll
            for (int q = 0; q < 5; q++) {
                As[pb][q * 4 + 0][tid] = pf[q].x;
                As[pb][q * 4 + 1][tid] = pf[q].y;
                As[pb][q * 4 + 2][tid] = pf[q].z;
                As[pb][q * 4 + 3][tid] = pf[q].w;
            }
        } else {
#pragma unroll
            for (int q = 0; q < 5; q++)
                *(float4*)&Bs[pb][q * 4 + brow][bcol] = pf[q];
        }
        __syncthreads();

        if (it + 1 < 15) {
            const int e0 = (it + 1) * PTK;
#pragma unroll
            for (int q = 0; q < 5; q++) {
                if (isA) pf[q] = *(const float4*)&emb[(long)av * EMB + e0 + q * 4];
                else     pf[q] = *(const float4*)&Wxh[(e0 + q * 4 + brow) * HID + bcol];
            }
        }

#pragma unroll
        for (int k = 0; k < PTK; k++) {
            float a[8], b[8];
            *(float4*)&a[0] = *(const float4*)&As[pb][k][tr * 8];
            *(float4*)&a[4] = *(const float4*)&As[pb][k][tr * 8 + 4];
            *(float4*)&b[0] = *(const float4*)&Bs[pb][k][tc * 8];
            *(float4*)&b[4] = *(const float4*)&Bs[pb][k][tc * 8 + 4];
#pragma unroll
            for (int i = 0; i < 8; i++)
#pragma unroll
                for (int j = 0; j < 8; j++) acc[i][j] += a[i] * b[j];
        }
        __syncthreads();
    }

#pragma unroll
    for (int i = 0; i < 8; i++) {
        const int v = v0 + tr * 8 + i;
        if (v < VOCAB) {
            *(float4*)&g_P[(long)v * HID + tc * 8]     = *(float4*)&acc[i][0];
            *(float4*)&g_P[(long)v * HID + tc * 8 + 4] = *(float4*)&acc[i][4];
        }
    }
}

// ---------------------------------------------------------------------------
// Kernel B: recurrence. grid=128, 256 threads = 8 warps = 2 rowgroups(16 rows)
// x 4 colgroups(32 cols) -> 2 warps/SMSP. Lane = 4 rows x 4 cols:
//   rsub = lane>>3 (rows rg2*16 + rsub*4..+3), csub = lane&7 (cols cgi*32+csub*4..+3)
// h layout: [k][row-pair] 64 B per k-row, per (rowgroup, buffer) = 8 KB.
// Per k per warp: 1 LDS.128 h (4x16B in 64B, conflict-free) + 1 LDS.128 w
// (8x16B = 128B) + 4 dup movs + 8 fma2  ->  fma2-pipe-bound with 2 warps/SMSP.
// Double-buffered h; ONE per-rowgroup named barrier (128 threads) per step.
// ---------------------------------------------------------------------------
__global__ __launch_bounds__(256, 1) void rnn_kernel(const int* __restrict__ x,
                                                     const float* __restrict__ Whh,
                                                     const float* __restrict__ bh,
                                                     const float* __restrict__ Wd,
                                                     const float* __restrict__ bd,
                                                     float* __restrict__ out) {
    extern __shared__ char smc[];
    float* Whh_sh = (float*)smc;                         // 65536 B
    char*  hbase  = smc + 65536;                         // 2 bufs x 2 rg x 8192 B
    int*   tok_sh = (int*)(smc + 65536 + 32768);         // 10240 B
    float* red    = (float*)(smc + 65536 + 32768 + 10240); // 32*4 floats

    const int tid  = threadIdx.x;
    const int lane = tid & 31;
    const int wid  = tid >> 5;
    const int rg2  = wid >> 2;        // rowgroup 0..1
    const int cgi  = wid & 3;         // colgroup 0..3
    const int rsub = lane >> 3;       // 0..3
    const int csub = lane & 7;        // 0..7
    const int c0   = cgi * 32 + csub * 4;     // this lane's 4 cols
    const int rloc = rg2 * 16 + rsub * 4;     // local row base (0..28)
    const int b0   = blockIdx.x * 32;

    // ---- init: Whh + tokens into smem ----
    {
        const float4* s = (const float4*)Whh;
        float4* d = (float4*)Whh_sh;
        for (int i = tid; i < HID * HID / 4; i += 256) d[i] = s[i];
        const int4* xs = (const int4*)(x + b0 * SEQ);
        int4* td = (int4*)tok_sh;
        for (int i = tid; i < 32 * SEQ / 4; i += 256) td[i] = xs[i];
    }
    __syncthreads();

    const float4 bh4 = *(const float4*)(bh + c0);
    ull bhd[4] = {pk(bh4.x, bh4.x), pk(bh4.y, bh4.y), pk(bh4.z, bh4.z), pk(bh4.w, bh4.w)};

    // prefetch t=0 inputs: P[tok][c0..c0+3] for this lane's 4 rows
    float4 xraw[4];
#pragma unroll
    for (int r = 0; r < 4; r++) {
        const int tk = tok_sh[(rloc + r) * SEQ + 0];
        xraw[r] = *(const float4*)(g_P + tk * HID + c0);
    }

    ull tv[2][4];   // tanh pairs: tv[p][c] = (h[r_{2p}], h[r_{2p+1}]) for col c0+c
#pragma unroll
    for (int p = 0; p < 2; p++)
#pragma unroll
        for (int c = 0; c < 4; c++) tv[p][c] = 0ull;

    // h read base for this lane (rsub offset folded in)
    const int hb_rg = rg2 * 8192 + rsub * 16;

    for (int t = 0; t < SEQ; t++) {
        ull acc[2][4];
        {
            const float* x0 = (const float*)&xraw[0];
            const float* x1 = (const float*)&xraw[1];
            const float* x2 = (const float*)&xraw[2];
            const float* x3 = (const float*)&xraw[3];
#pragma unroll
            for (int c = 0; c < 4; c++) {
                acc[0][c] = add2(pk(x0[c], x1[c]), bhd[c]);
                acc[1][c] = add2(pk(x2[c], x3[c]), bhd[c]);
            }
        }

        // prefetch next timestep's P rows
        if (t + 1 < SEQ) {
#pragma unroll
            for (int r = 0; r < 4; r++) {
                const int tk = tok_sh[(rloc + r) * SEQ + t + 1];
                xraw[r] = *(const float4*)(g_P + tk * HID + c0);
            }
        }

        if (t > 0) {
            const char*  hb = hbase + ((t + 1) & 1) * 16384 + hb_rg;   // h(t-1)
            const float* wp = Whh_sh + c0;
#pragma unroll 1
            for (int ko = 0; ko < 8; ko++) {
#pragma unroll
                for (int kk = 0; kk < 16; kk++) {
                    const int k = ko * 16 + kk;
                    const ulonglong2 hp = *(const ulonglong2*)(hb + k * 64);
                    const float4 w = *(const float4*)(wp + k * HID);
                    const ull w0 = pk(w.x, w.x), w1 = pk(w.y, w.y);
                    const ull w2 = pk(w.z, w.z), w3 = pk(w.w, w.w);
                    acc[0][0] = fma2(hp.x, w0, acc[0][0]);
                    acc[0][1] = fma2(hp.x, w1, acc[0][1]);
                    acc[0][2] = fma2(hp.x, w2, acc[0][2]);
                    acc[0][3] = fma2(hp.x, w3, acc[0][3]);
                    acc[1][0] = fma2(hp.y, w0, acc[1][0]);
                    acc[1][1] = fma2(hp.y, w1, acc[1][1]);
                    acc[1][2] = fma2(hp.y, w2, acc[1][2]);
                    acc[1][3] = fma2(hp.y, w3, acc[1][3]);
                }
            }
        }

        // tanh -> tv (pairs stay packed)
#pragma unroll
        for (int p = 0; p < 2; p++)
#pragma unroll
            for (int c = 0; c < 4; c++) {
                float2 a = upk(acc[p][c]);
                tv[p][c] = pk(ftanh(a.x), ftanh(a.y));
            }

        // store h(t): for each of lane's 4 cols (as k-index), 16B = 4 rows
        {
            char* hw = hbase + (t & 1) * 16384 + hb_rg;
#pragma unroll
            for (int i = 0; i < 4; i++) {
                ulonglong2 v; v.x = tv[0][i]; v.y = tv[1][i];
                *(ulonglong2*)(hw + (c0 + i) * 64) = v;
            }
        }
        // rowgroup barrier (4 warps, 128 threads)
        asm volatile("bar.sync %0, %1;" :: "r"(rg2 + 1), "r"(128) : "memory");
    }

    // ---- Dense(1) + sigmoid ----
    const float4 wd4 = *(const float4*)(Wd + c0);
    const float* wdp = (const float*)&wd4;
    float pr[4];
#pragma unroll
    for (int r = 0; r < 4; r++) pr[r] = 0.f;
#pragma unroll
    for (int c = 0; c < 4; c++) {
        float2 v0 = upk(tv[0][c]);
        float2 v1 = upk(tv[1][c]);
        pr[0] += v0.x * wdp[c];
        pr[1] += v0.y * wdp[c];
        pr[2] += v1.x * wdp[c];
        pr[3] += v1.y * wdp[c];
    }
    // reduce over csub (8 lanes within each rsub group)
#pragma unroll
    for (int off = 1; off < 8; off <<= 1)
#pragma unroll
        for (int r = 0; r < 4; r++)
            pr[r] += __shfl_xor_sync(0xffffffff, pr[r], off);
    if (csub == 0) {
#pragma unroll
        for (int r = 0; r < 4; r++)
            red[(rloc + r) * 4 + cgi] = pr[r];
    }
    __syncthreads();
    if (tid < 32) {
        const float s = red[tid * 4] + red[tid * 4 + 1] + red[tid * 4 + 2]
                      + red[tid * 4 + 3] + bd[0];
        out[b0 + tid] = __fdividef(1.f, 1.f + __expf(-s));
    }
}

// ---------------------------------------------------------------------------
extern "C" void kernel_launch(void* const* d_in, const int* in_sizes, int n_in,
                              void* d_out, int out_size) {
    const int*   x   = (const int*)d_in[0];
    const float* emb = (const float*)d_in[1];
    const float* Wxh = (const float*)d_in[2];
    const float* Whh = (const float*)d_in[3];
    const float* bh  = (const float*)d_in[4];
    const float* Wd  = (const float*)d_in[5];
    const float* bd  = (const float*)d_in[6];
    float* out = (float*)d_out;

    proj_kernel<<<(VOCAB + 127) / 128, 256>>>(emb, Wxh);

    const int smem = 65536 + 32768 + 10240 + 32 * 4 * 4;   // 109056 B
    cudaFuncSetAttribute(rnn_kernel, cudaFuncAttributeMaxDynamicSharedMemorySize, smem);
    rnn_kernel<<<BATCH / 32, 256, smem>>>(x, Whh, bh, Wd, bd, out);
}

// round 10
// speedup vs baseline: 1.2245x; 1.1898x over previous
#include <cuda_runtime.h>
#include <math.h>
#include <stdint.h>

#define VOCAB 50000
#define EMB   300
#define SEQ   80
#define HID   128
#define BATCH 4096

typedef unsigned long long ull;

// Scratch: projected embedding table P = emb @ Wxh (25.6 MB, L2-resident at use)
__device__ float g_P[VOCAB * HID];

// ---- packed f32x2 helpers ----
__device__ __forceinline__ ull fma2(ull a, ull b, ull c) {
    ull d; asm("fma.rn.f32x2 %0, %1, %2, %3;" : "=l"(d) : "l"(a), "l"(b), "l"(c)); return d;
}
__device__ __forceinline__ ull add2(ull a, ull b) {
    ull d; asm("add.rn.f32x2 %0, %1, %2;" : "=l"(d) : "l"(a), "l"(b)); return d;
}
__device__ __forceinline__ ull pk(float lo, float hi) {
    ull d; asm("mov.b64 %0, {%1, %2};" : "=l"(d) : "f"(lo), "f"(hi)); return d;
}
__device__ __forceinline__ float2 upk(ull v) {
    float2 r; asm("mov.b64 {%0, %1}, %2;" : "=f"(r.x), "=f"(r.y) : "l"(v)); return r;
}
__device__ __forceinline__ float ftanh(float x) {
    float xc = fminf(fmaxf(x, -15.f), 15.f);
    float e  = __expf(2.f * xc);
    return __fdividef(e - 1.f, e + 1.f);
}

// ---------------------------------------------------------------------------
// Kernel A: P[v][j] = sum_e emb[v][e] * Wxh[e][j]
// R4 inner body (PTK=20, double-buffered, 1 sync/iter) wrapped in a 3-subtile
// outer loop: grid=131 blocks * 3 subtiles * 128 rows = 50304 >= 50000.
// Single wave (131 <= 148 SMs) -> removes the 1.32-wave tail of grid=391.
// ---------------------------------------------------------------------------
#define PTK 20

__global__ __launch_bounds__(256) void proj_kernel(const float* __restrict__ emb,
                                                   const float* __restrict__ Wxh) {
    __shared__ float As[2][PTK][128];   // [buf][k][row]
    __shared__ float Bs[2][PTK][128];   // [buf][k][col]

    const int tid = threadIdx.x;
    const int tr  = tid >> 4;   // rows tr*8..+7
    const int tc  = tid & 15;   // cols tc*8..+7

    const bool isA = (tid < 128);
    const int t2   = tid - 128;
    const int brow = t2 >> 5;        // 0..3
    const int bcol = (t2 & 31) * 4;

    for (int sub = 0; sub < 3; sub++) {
        const int v0 = (blockIdx.x * 3 + sub) * 128;
        if (v0 >= VOCAB) break;   // block-uniform

        float acc[8][8];
#pragma unroll
        for (int i = 0; i < 8; i++)
#pragma unroll
            for (int j = 0; j < 8; j++) acc[i][j] = 0.f;

        int av = v0 + tid; if (av > VOCAB - 1) av = VOCAB - 1;  // clamped junk, discarded

        float4 pf[5];
#pragma unroll
        for (int q = 0; q < 5; q++) {
            if (isA) pf[q] = *(const float4*)&emb[(long)av * EMB + 0 + q * 4];
            else     pf[q] = *(const float4*)&Wxh[(0 + q * 4 + brow) * HID + bcol];
        }

        for (int it = 0; it < 15; it++) {
            const int pb = it & 1;
            if (isA) {
#pragma unroll
                for (int q = 0; q < 5; q++) {
                    As[pb][q * 4 + 0][tid] = pf[q].x;
                    As[pb][q * 4 + 1][tid] = pf[q].y;
                    As[pb][q * 4 + 2][tid] = pf[q].z;
                    As[pb][q * 4 + 3][tid] = pf[q].w;
                }
            } else {
#pragma unroll
                for (int q = 0; q < 5; q++)
                    *(float4*)&Bs[pb][q * 4 + brow][bcol] = pf[q];
            }
            __syncthreads();

            if (it + 1 < 15) {
                const int e0 = (it + 1) * PTK;
#pragma unroll
                for (int q = 0; q < 5; q++) {
                    if (isA) pf[q] = *(const float4*)&emb[(long)av * EMB + e0 + q * 4];
                    else     pf[q] = *(const float4*)&Wxh[(e0 + q * 4 + brow) * HID + bcol];
                }
            }

#pragma unroll
            for (int k = 0; k < PTK; k++) {
                float a[8], b[8];
                *(float4*)&a[0] = *(const float4*)&As[pb][k][tr * 8];
                *(float4*)&a[4] = *(const float4*)&As[pb][k][tr * 8 + 4];
                *(float4*)&b[0] = *(const float4*)&Bs[pb][k][tc * 8];
                *(float4*)&b[4] = *(const float4*)&Bs[pb][k][tc * 8 + 4];
#pragma unroll
                for (int i = 0; i < 8; i++)
#pragma unroll
                    for (int j = 0; j < 8; j++) acc[i][j] += a[i] * b[j];
            }
            __syncthreads();
        }

#pragma unroll
        for (int i = 0; i < 8; i++) {
            const int v = v0 + tr * 8 + i;
            if (v < VOCAB) {
                *(float4*)&g_P[(long)v * HID + tc * 8]     = *(float4*)&acc[i][0];
                *(float4*)&g_P[(long)v * HID + tc * 8 + 4] = *(float4*)&acc[i][4];
            }
        }
    }
}

// ---------------------------------------------------------------------------
// Kernel B: recurrence — R4 winner VERBATIM except the k-loop processes 2 k's
// per straight-line group (6 loads batched, then 32 fma2). Same address math,
// same swizzle, same stores, no cross-iteration register state.
// grid=128, 128 threads (4 warps, 1/SMSP), warp-private h (4 KB swizzled).
// ---------------------------------------------------------------------------
__global__ __launch_bounds__(128, 1) void rnn_kernel(const int* __restrict__ x,
                                                     const float* __restrict__ Whh,
                                                     const float* __restrict__ bh,
                                                     const float* __restrict__ Wd,
                                                     const float* __restrict__ bd,
                                                     float* __restrict__ out) {
    extern __shared__ char smc[];
    float* Whh_sh = (float*)smc;                      // 65536 B
    float* hball  = (float*)(smc + 65536);            // 4 x 4096 B
    int*   tok_sh = (int*)(smc + 65536 + 16384);      // 10240 B

    const int tid  = threadIdx.x;
    const int lane = tid & 31;
    const int rg   = tid >> 5;
    const int j0   = lane * 4;
    const int b0   = blockIdx.x * 32;

    // ---- init: Whh + tokens into smem ----
    {
        const float4* s = (const float4*)Whh;
        float4* d = (float4*)Whh_sh;
        for (int i = tid; i < HID * HID / 4; i += 128) d[i] = s[i];
        const int4* xs = (const int4*)(x + b0 * SEQ);
        int4* td = (int4*)tok_sh;
        for (int i = tid; i < 32 * SEQ / 4; i += 128) td[i] = xs[i];
    }
    __syncthreads();

    char* hw = (char*)(hball + rg * 1024);
    const int* myTok = tok_sh + (rg * 8) * SEQ;

    uint32_t st_off[4][2];
#pragma unroll
    for (int c = 0; c < 4; c++)
#pragma unroll
        for (int hh = 0; hh < 2; hh++)
            st_off[c][hh] = (uint32_t)((8 * lane + ((2 * c + hh) ^ (lane & 7))) * 16);

    const float4 bh4 = *(const float4*)(bh + j0);
    ull bhd[4] = {pk(bh4.x, bh4.x), pk(bh4.y, bh4.y), pk(bh4.z, bh4.z), pk(bh4.w, bh4.w)};

    float4 xraw[8];
#pragma unroll
    for (int r = 0; r < 8; r++) {
        const int tk = myTok[r * SEQ + 0];
        xraw[r] = *(const float4*)(g_P + tk * HID + j0);
    }

    for (int t = 0; t < SEQ; t++) {
        ull acc[4][4];
#pragma unroll
        for (int p = 0; p < 4; p++) {
            const float* lo = (const float*)&xraw[2 * p];
            const float* hi = (const float*)&xraw[2 * p + 1];
#pragma unroll
            for (int c = 0; c < 4; c++)
                acc[p][c] = add2(pk(lo[c], hi[c]), bhd[c]);
        }

        if (t + 1 < SEQ) {
#pragma unroll
            for (int r = 0; r < 8; r++) {
                const int tk = myTok[r * SEQ + t + 1];
                xraw[r] = *(const float4*)(g_P + tk * HID + j0);
            }
        }

        if (t > 0) {
            const char*  hb = hw;
            const float* wp = Whh_sh + j0;
#pragma unroll 1
            for (int j = 0; j < 4; j++) {
#pragma unroll
                for (int i = 0; i < 32; i += 2) {
                    const int i1   = i + 1;
                    const int offA = ((2 * i)  ^ ((i  >> 2) & 7)) * 16;
                    const int offB = ((2 * i1) ^ ((i1 >> 2) & 7)) * 16;
                    // batch all 6 loads for k=i and k=i+1
                    ulonglong2 hA0 = *(const ulonglong2*)(hb + offA);
                    ulonglong2 hB0 = *(const ulonglong2*)(hb + (offA ^ 16));
                    float4     wv0 = *(const float4*)(wp + i * HID);
                    ulonglong2 hA1 = *(const ulonglong2*)(hb + offB);
                    ulonglong2 hB1 = *(const ulonglong2*)(hb + (offB ^ 16));
                    float4     wv1 = *(const float4*)(wp + i1 * HID);
                    // k = i
                    {
                        const ull w0 = pk(wv0.x, wv0.x), w1 = pk(wv0.y, wv0.y);
                        const ull w2 = pk(wv0.z, wv0.z), w3 = pk(wv0.w, wv0.w);
                        acc[0][0] = fma2(hA0.x, w0, acc[0][0]);
                        acc[0][1] = fma2(hA0.x, w1, acc[0][1]);
                        acc[0][2] = fma2(hA0.x, w2, acc[0][2]);
                        acc[0][3] = fma2(hA0.x, w3, acc[0][3]);
                        acc[1][0] = fma2(hA0.y, w0, acc[1][0]);
                        acc[1][1] = fma2(hA0.y, w1, acc[1][1]);
                        acc[1][2] = fma2(hA0.y, w2, acc[1][2]);
                        acc[1][3] = fma2(hA0.y, w3, acc[1][3]);
                        acc[2][0] = fma2(hB0.x, w0, acc[2][0]);
                        acc[2][1] = fma2(hB0.x, w1, acc[2][1]);
                        acc[2][2] = fma2(hB0.x, w2, acc[2][2]);
                        acc[2][3] = fma2(hB0.x, w3, acc[2][3]);
                        acc[3][0] = fma2(hB0.y, w0, acc[3][0]);
                        acc[3][1] = fma2(hB0.y, w1, acc[3][1]);
                        acc[3][2] = fma2(hB0.y, w2, acc[3][2]);
                        acc[3][3] = fma2(hB0.y, w3, acc[3][3]);
                    }
                    // k = i+1
                    {
                        const ull w0 = pk(wv1.x, wv1.x), w1 = pk(wv1.y, wv1.y);
                        const ull w2 = pk(wv1.z, wv1.z), w3 = pk(wv1.w, wv1.w);
                        acc[0][0] = fma2(hA1.x, w0, acc[0][0]);
                        acc[0][1] = fma2(hA1.x, w1, acc[0][1]);
                        acc[0][2] = fma2(hA1.x, w2, acc[0][2]);
                        acc[0][3] = fma2(hA1.x, w3, acc[0][3]);
                        acc[1][0] = fma2(hA1.y, w0, acc[1][0]);
                        acc[1][1] = fma2(hA1.y, w1, acc[1][1]);
                        acc[1][2] = fma2(hA1.y, w2, acc[1][2]);
                        acc[1][3] = fma2(hA1.y, w3, acc[1][3]);
                        acc[2][0] = fma2(hB1.x, w0, acc[2][0]);
                        acc[2][1] = fma2(hB1.x, w1, acc[2][1]);
                        acc[2][2] = fma2(hB1.x, w2, acc[2][2]);
                        acc[2][3] = fma2(hB1.x, w3, acc[2][3]);
                        acc[3][0] = fma2(hB1.y, w0, acc[3][0]);
                        acc[3][1] = fma2(hB1.y, w1, acc[3][1]);
                        acc[3][2] = fma2(hB1.y, w2, acc[3][2]);
                        acc[3][3] = fma2(hB1.y, w3, acc[3][3]);
                    }
                }
                hb += 1024;
                wp += 32 * HID;
            }
        }

        __syncwarp();
        // tanh + store h(t) into warp-private buffer (R4 verbatim)
#pragma unroll
        for (int c = 0; c < 4; c++) {
            float2 a0 = upk(acc[0][c]), a1 = upk(acc[1][c]);
            float2 a2 = upk(acc[2][c]), a3 = upk(acc[3][c]);
            float4 v0, v1;
            v0.x = ftanh(a0.x); v0.y = ftanh(a0.y);
            v0.z = ftanh(a1.x); v0.w = ftanh(a1.y);
            v1.x = ftanh(a2.x); v1.y = ftanh(a2.y);
            v1.z = ftanh(a3.x); v1.w = ftanh(a3.y);
            *(float4*)(hw + st_off[c][0]) = v0;
            *(float4*)(hw + st_off[c][1]) = v1;
        }
        __syncwarp();
    }

    // ---- Dense(1) + sigmoid (R4 verbatim) ----
    const float4 wd4 = *(const float4*)(Wd + j0);
    const float* wdp = (const float*)&wd4;
    const float  bd0 = bd[0];
    float part[8];
#pragma unroll
    for (int r = 0; r < 8; r++) part[r] = 0.f;
#pragma unroll
    for (int c = 0; c < 4; c++) {
        float4 v0 = *(const float4*)(hw + st_off[c][0]);
        float4 v1 = *(const float4*)(hw + st_off[c][1]);
        const float wc = wdp[c];
        part[0] += v0.x * wc; part[1] += v0.y * wc;
        part[2] += v0.z * wc; part[3] += v0.w * wc;
        part[4] += v1.x * wc; part[5] += v1.y * wc;
        part[6] += v1.z * wc; part[7] += v1.w * wc;
    }
#pragma unroll
    for (int off = 16; off > 0; off >>= 1)
#pragma unroll
        for (int r = 0; r < 8; r++)
            part[r] += __shfl_xor_sync(0xffffffff, part[r], off);
    if (lane == 0) {
#pragma unroll
        for (int r = 0; r < 8; r++)
            out[b0 + rg * 8 + r] = __fdividef(1.f, 1.f + __expf(-(part[r] + bd0)));
    }
}

// ---------------------------------------------------------------------------
extern "C" void kernel_launch(void* const* d_in, const int* in_sizes, int n_in,
                              void* d_out, int out_size) {
    const int*   x   = (const int*)d_in[0];
    const float* emb = (const float*)d_in[1];
    const float* Wxh = (const float*)d_in[2];
    const float* Whh = (const float*)d_in[3];
    const float* bh  = (const float*)d_in[4];
    const float* Wd  = (const float*)d_in[5];
    const float* bd  = (const float*)d_in[6];
    float* out = (float*)d_out;

    proj_kernel<<<131, 256>>>(emb, Wxh);

    const int smem = 65536 + 16384 + 32 * SEQ * 4;   // 92160 B
    cudaFuncSetAttribute(rnn_kernel, cudaFuncAttributeMaxDynamicSharedMemorySize, smem);
    rnn_kernel<<<BATCH / 32, 128, smem>>>(x, Whh, bh, Wd, bd, out);
}

// round 11
// speedup vs baseline: 1.9063x; 1.5568x over previous
#include <cuda_runtime.h>
#include <cuda_fp16.h>
#include <math.h>
#include <stdint.h>

#define VOCAB 50000
#define EMB   300
#define SEQ   80
#define HID   128
#define BATCH 4096

typedef unsigned long long ull;

// Scratch: projected embedding table P = emb @ Wxh (25.6 MB, L2-resident at use)
__device__ float g_P[VOCAB * HID];

__device__ __forceinline__ uint32_t su32(const void* p) {
    uint32_t a;
    asm("{ .reg .u64 t; cvta.to.shared.u64 t, %1; cvt.u32.u64 %0, t; }" : "=r"(a) : "l"(p));
    return a;
}
__device__ __forceinline__ float ftanh(float x) {
    float e = __expf(2.f * x);
    return 1.f - __fdividef(2.f, e + 1.f);
}
__device__ __forceinline__ uint32_t pkh(float a, float b) {
    __half2 h = __halves2half2(__float2half_rn(a), __float2half_rn(b));
    return *reinterpret_cast<uint32_t*>(&h);
}

// ---------------------------------------------------------------------------
// Kernel A: P[v][j] = sum_e emb[v][e] * Wxh[e][j]
// (exact R4-winner version: PTK=20, double-buffered, 1 sync/iter, grid=391)
// ---------------------------------------------------------------------------
#define PTK 20

__global__ __launch_bounds__(256) void proj_kernel(const float* __restrict__ emb,
                                                   const float* __restrict__ Wxh) {
    __shared__ float As[2][PTK][128];
    __shared__ float Bs[2][PTK][128];

    const int tid = threadIdx.x;
    const int v0  = blockIdx.x * 128;
    const int tr  = tid >> 4;
    const int tc  = tid & 15;

    float acc[8][8];
#pragma unroll
    for (int i = 0; i < 8; i++)
#pragma unroll
        for (int j = 0; j < 8; j++) acc[i][j] = 0.f;

    const bool isA = (tid < 128);
    int av = v0 + tid; if (av > VOCAB - 1) av = VOCAB - 1;
    const int t2   = tid - 128;
    const int brow = t2 >> 5;
    const int bcol = (t2 & 31) * 4;

    float4 pf[5];
#pragma unroll
    for (int q = 0; q < 5; q++) {
        if (isA) pf[q] = *(const float4*)&emb[(long)av * EMB + 0 + q * 4];
        else     pf[q] = *(const float4*)&Wxh[(0 + q * 4 + brow) * HID + bcol];
    }

    for (int it = 0; it < 15; it++) {
        const int pb = it & 1;
        if (isA) {
#pragma unroll
            for (int q = 0; q < 5; q++) {
                As[pb][q * 4 + 0][tid] = pf[q].x;
                As[pb][q * 4 + 1][tid] = pf[q].y;
                As[pb][q * 4 + 2][tid] = pf[q].z;
                As[pb][q * 4 + 3][tid] = pf[q].w;
            }
        } else {
#pragma unroll
            for (int q = 0; q < 5; q++)
                *(float4*)&Bs[pb][q * 4 + brow][bcol] = pf[q];
        }
        __syncthreads();

        if (it + 1 < 15) {
            const int e0 = (it + 1) * PTK;
#pragma unroll
            for (int q = 0; q < 5; q++) {
                if (isA) pf[q] = *(const float4*)&emb[(long)av * EMB + e0 + q * 4];
                else     pf[q] = *(const float4*)&Wxh[(e0 + q * 4 + brow) * HID + bcol];
            }
        }

#pragma unroll
        for (int k = 0; k < PTK; k++) {
            float a[8], b[8];
            *(float4*)&a[0] = *(const float4*)&As[pb][k][tr * 8];
            *(float4*)&a[4] = *(const float4*)&As[pb][k][tr * 8 + 4];
            *(float4*)&b[0] = *(const float4*)&Bs[pb][k][tc * 8];
            *(float4*)&b[4] = *(const float4*)&Bs[pb][k][tc * 8 + 4];
#pragma unroll
            for (int i = 0; i < 8; i++)
#pragma unroll
                for (int j = 0; j < 8; j++) acc[i][j] += a[i] * b[j];
        }
        __syncthreads();
    }

#pragma unroll
    for (int i = 0; i < 8; i++) {
        const int v = v0 + tr * 8 + i;
        if (v < VOCAB) {
            *(float4*)&g_P[(long)v * HID + tc * 8]     = *(float4*)&acc[i][0];
            *(float4*)&g_P[(long)v * HID + tc * 8 + 4] = *(float4*)&acc[i][4];
        }
    }
}

// ---------------------------------------------------------------------------
// Kernel B: tensor-core recurrence. grid=128, 256 threads = 8 warps:
// warp(wr,wc): rows wr*16..+15 (of 32/block), cols wc*32..+31.
// mma.sync.m16n8k16 f16f16+f32, hi/lo split of h AND Whh (3 products, ll
// dropped ~2^-22). B-fragments of Whh extracted once into regs (128/lane).
// h hi/lo in smem [32 rows][136 halves] (272B pitch: conflict-free STS.32 +
// ldmatrix), double-buffered; ONE __syncthreads per step.
//
// Fragment maps (PTX m16n8k16, g=lane>>2, q=lane&3):
//   A: a0=(g,2q|2q+1) a1=(g+8,..) a2=(g,2q+8..) a3=(g+8,2q+8..)
//   B: b0=(k=2q,2q+1; n=g)  b1=(k=2q+8,2q+9; n=g)
//   D: d0=(g,2q) d1=(g,2q+1) d2=(g+8,2q) d3=(g+8,2q+1)
// ---------------------------------------------------------------------------
#define HPITCH 272          // bytes per h row (136 halves)
#define HSEG   8704         // 32 rows * 272
// smem: [0,34816) h bufs: buf0_hi@0 buf0_lo@8704 buf1_hi@17408 buf1_lo@26112
//       [34816,35328) red[32][4]
//       [65536,75776) tok  (Whh fp32 occupies [0,65536) during init only)

__global__ __launch_bounds__(256, 1) void rnn_tc_kernel(const int* __restrict__ x,
                                                        const float* __restrict__ Whh,
                                                        const float* __restrict__ bh,
                                                        const float* __restrict__ Wd,
                                                        const float* __restrict__ bd,
                                                        float* __restrict__ out) {
    extern __shared__ char smc[];
    float* Whh_sh = (float*)smc;
    int*   tok_sh = (int*)(smc + 65536);
    char*  hbase  = smc;
    float* red    = (float*)(smc + 34816);

    const int tid  = threadIdx.x;
    const int lane = tid & 31;
    const int wid  = tid >> 5;
    const int wr   = wid >> 2;       // 0..1
    const int wc   = wid & 3;        // 0..3
    const int g    = lane >> 2;      // 0..7
    const int q    = lane & 3;       // 0..3
    const int b0   = blockIdx.x * 32;

    // ---- init: Whh fp32 + tokens ----
    {
        const float4* s = (const float4*)Whh;
        float4* d = (float4*)Whh_sh;
        for (int i = tid; i < HID * HID / 4; i += 256) d[i] = s[i];
        const int4* xs = (const int4*)(x + b0 * SEQ);
        int4* td = (int4*)tok_sh;
        for (int i = tid; i < 32 * SEQ / 4; i += 256) td[i] = xs[i];
    }
    __syncthreads();

    // ---- extract B fragments (hi/lo) into registers ----
    uint32_t Bh[8][4][2], Bl[8][4][2];
#pragma unroll
    for (int s = 0; s < 8; s++) {
        const int k0 = s * 16 + 2 * q;
#pragma unroll
        for (int n = 0; n < 4; n++) {
            const int nc = wc * 32 + n * 8 + g;
            float w00 = Whh_sh[(k0)     * HID + nc];
            float w01 = Whh_sh[(k0 + 1) * HID + nc];
            float w10 = Whh_sh[(k0 + 8) * HID + nc];
            float w11 = Whh_sh[(k0 + 9) * HID + nc];
            float h00 = __half2float(__float2half_rn(w00));
            float h01 = __half2float(__float2half_rn(w01));
            float h10 = __half2float(__float2half_rn(w10));
            float h11 = __half2float(__float2half_rn(w11));
            Bh[s][n][0] = pkh(h00, h01);
            Bh[s][n][1] = pkh(h10, h11);
            Bl[s][n][0] = pkh(w00 - h00, w01 - h01);
            Bl[s][n][1] = pkh(w10 - h10, w11 - h11);
        }
    }
    __syncthreads();   // Whh_sh region now free for h buffers

    // per-lane constants
    float2 bh2[4];
#pragma unroll
    for (int n = 0; n < 4; n++)
        bh2[n] = *(const float2*)&bh[wc * 32 + n * 8 + 2 * q];

    const int rowA = wr * 16 + g;         // local row for d0/d1
    const int rowB = rowA + 8;            // local row for d2/d3
    const uint32_t smem_u32 = su32(smc);
    // ldmatrix lane address offset (within a hi/lo segment, before slab offset)
    const uint32_t lm_off = (uint32_t)((wr * 16 + (lane & 15)) * HPITCH + (lane >> 4) * 16);
    // store byte offsets (within segment): row*272 + col*2
    uint32_t stA[4], stB[4];
#pragma unroll
    for (int n = 0; n < 4; n++) {
        const int col = wc * 32 + n * 8 + 2 * q;
        stA[n] = (uint32_t)(rowA * HPITCH + col * 2);
        stB[n] = (uint32_t)(rowB * HPITCH + col * 2);
    }

    // prefetch t=0 inputs
    float2 xp[2][4];
    {
        const int tkA = tok_sh[rowA * SEQ + 0];
        const int tkB = tok_sh[rowB * SEQ + 0];
#pragma unroll
        for (int n = 0; n < 4; n++) {
            xp[0][n] = *(const float2*)&g_P[tkA * HID + wc * 32 + n * 8 + 2 * q];
            xp[1][n] = *(const float2*)&g_P[tkB * HID + wc * 32 + n * 8 + 2 * q];
        }
    }

    float v[4][4];   // tanh values, persists to epilogue

    for (int t = 0; t < SEQ; t++) {
        float acc[4][4];
#pragma unroll
        for (int n = 0; n < 4; n++) {
            acc[n][0] = xp[0][n].x + bh2[n].x;
            acc[n][1] = xp[0][n].y + bh2[n].y;
            acc[n][2] = xp[1][n].x + bh2[n].x;
            acc[n][3] = xp[1][n].y + bh2[n].y;
        }

        if (t + 1 < SEQ) {
            const int tkA = tok_sh[rowA * SEQ + t + 1];
            const int tkB = tok_sh[rowB * SEQ + t + 1];
#pragma unroll
            for (int n = 0; n < 4; n++) {
                xp[0][n] = *(const float2*)&g_P[tkA * HID + wc * 32 + n * 8 + 2 * q];
                xp[1][n] = *(const float2*)&g_P[tkB * HID + wc * 32 + n * 8 + 2 * q];
            }
        }

        if (t > 0) {
            const uint32_t hseg = smem_u32 + ((t + 1) & 1) * (2 * HSEG);  // buf (t-1)&1
#pragma unroll
            for (int s = 0; s < 8; s++) {
                uint32_t Ah[4], Al[4];
                asm volatile("ldmatrix.sync.aligned.m8n8.x4.shared.b16 {%0,%1,%2,%3}, [%4];"
                             : "=r"(Ah[0]), "=r"(Ah[1]), "=r"(Ah[2]), "=r"(Ah[3])
                             : "r"(hseg + lm_off + s * 32));
                asm volatile("ldmatrix.sync.aligned.m8n8.x4.shared.b16 {%0,%1,%2,%3}, [%4];"
                             : "=r"(Al[0]), "=r"(Al[1]), "=r"(Al[2]), "=r"(Al[3])
                             : "r"(hseg + HSEG + lm_off + s * 32));
#pragma unroll
                for (int n = 0; n < 4; n++) {
                    asm volatile(
                        "mma.sync.aligned.m16n8k16.row.col.f32.f16.f16.f32 "
                        "{%0,%1,%2,%3}, {%4,%5,%6,%7}, {%8,%9}, {%0,%1,%2,%3};"
                        : "+f"(acc[n][0]), "+f"(acc[n][1]), "+f"(acc[n][2]), "+f"(acc[n][3])
                        : "r"(Ah[0]), "r"(Ah[1]), "r"(Ah[2]), "r"(Ah[3]),
                          "r"(Bh[s][n][0]), "r"(Bh[s][n][1]));
                    asm volatile(
                        "mma.sync.aligned.m16n8k16.row.col.f32.f16.f16.f32 "
                        "{%0,%1,%2,%3}, {%4,%5,%6,%7}, {%8,%9}, {%0,%1,%2,%3};"
                        : "+f"(acc[n][0]), "+f"(acc[n][1]), "+f"(acc[n][2]), "+f"(acc[n][3])
                        : "r"(Ah[0]), "r"(Ah[1]), "r"(Ah[2]), "r"(Ah[3]),
                          "r"(Bl[s][n][0]), "r"(Bl[s][n][1]));
                    asm volatile(
                        "mma.sync.aligned.m16n8k16.row.col.f32.f16.f16.f32 "
                        "{%0,%1,%2,%3}, {%4,%5,%6,%7}, {%8,%9}, {%0,%1,%2,%3};"
                        : "+f"(acc[n][0]), "+f"(acc[n][1]), "+f"(acc[n][2]), "+f"(acc[n][3])
                        : "r"(Al[0]), "r"(Al[1]), "r"(Al[2]), "r"(Al[3]),
                          "r"(Bh[s][n][0]), "r"(Bh[s][n][1]));
                }
            }
        }

        // tanh
#pragma unroll
        for (int n = 0; n < 4; n++)
#pragma unroll
            for (int d = 0; d < 4; d++)
                v[n][d] = ftanh(acc[n][d]);

        // store h(t) hi/lo to buf t&1
        {
            char* ws = hbase + (t & 1) * (2 * HSEG);
#pragma unroll
            for (int n = 0; n < 4; n++) {
                float h0 = __half2float(__float2half_rn(v[n][0]));
                float h1 = __half2float(__float2half_rn(v[n][1]));
                float h2 = __half2float(__float2half_rn(v[n][2]));
                float h3 = __half2float(__float2half_rn(v[n][3]));
                *(uint32_t*)(ws + stA[n])        = pkh(h0, h1);
                *(uint32_t*)(ws + HSEG + stA[n]) = pkh(v[n][0] - h0, v[n][1] - h1);
                *(uint32_t*)(ws + stB[n])        = pkh(h2, h3);
                *(uint32_t*)(ws + HSEG + stB[n]) = pkh(v[n][2] - h2, v[n][3] - h3);
            }
        }
        __syncthreads();
    }

    // ---- Dense(1) + sigmoid ----
    float pA = 0.f, pB = 0.f;
#pragma unroll
    for (int n = 0; n < 4; n++) {
        const float2 wd2 = *(const float2*)&Wd[wc * 32 + n * 8 + 2 * q];
        pA += v[n][0] * wd2.x + v[n][1] * wd2.y;
        pB += v[n][2] * wd2.x + v[n][3] * wd2.y;
    }
    pA += __shfl_xor_sync(0xffffffff, pA, 1);
    pA += __shfl_xor_sync(0xffffffff, pA, 2);
    pB += __shfl_xor_sync(0xffffffff, pB, 1);
    pB += __shfl_xor_sync(0xffffffff, pB, 2);
    if (q == 0) {
        red[rowA * 4 + wc] = pA;
        red[rowB * 4 + wc] = pB;
    }
    __syncthreads();
    if (tid < 32) {
        const float s = red[tid * 4] + red[tid * 4 + 1] + red[tid * 4 + 2]
                      + red[tid * 4 + 3] + bd[0];
        out[b0 + tid] = __fdividef(1.f, 1.f + __expf(-s));
    }
}

// ---------------------------------------------------------------------------
extern "C" void kernel_launch(void* const* d_in, const int* in_sizes, int n_in,
                              void* d_out, int out_size) {
    const int*   x   = (const int*)d_in[0];
    const float* emb = (const float*)d_in[1];
    const float* Wxh = (const float*)d_in[2];
    const float* Whh = (const float*)d_in[3];
    const float* bh  = (const float*)d_in[4];
    const float* Wd  = (const float*)d_in[5];
    const float* bd  = (const float*)d_in[6];
    float* out = (float*)d_out;

    proj_kernel<<<(VOCAB + 127) / 128, 256>>>(emb, Wxh);

    const int smem = 65536 + 32 * SEQ * 4;   // 75776 B
    cudaFuncSetAttribute(rnn_tc_kernel, cudaFuncAttributeMaxDynamicSharedMemorySize, smem);
    rnn_tc_kernel<<<BATCH / 32, 256, smem>>>(x, Whh, bh, Wd, bd, out);
}